// round 12
// baseline (speedup 1.0000x reference)
#include <cuda_runtime.h>
#include <cooperative_groups.h>
namespace cg = cooperative_groups;

#define NB 4
#define NPTS 32768
#define NS 1024
#define NK 32
#define ND 64
#define NSAMP_TOT (NB*NS*NK)   // 131072
#define R2 0.04f

// ---------------- device scratch (static, allowed) ----------------
__device__ float4 g_xyz4[NB*NPTS];                    // x,y,z, |p|^2
__device__ float  g_ptsT[(size_t)NB*NPTS*ND];         // [b][n][c]
__device__ float4 g_newxyz[NB*NS];                    // centroid + |c|^2
__device__ int    g_ballidx[NB*NS*NK];
__device__ float  g_z1[(size_t)NSAMP_TOT*64];
__device__ float  g_z2[(size_t)NSAMP_TOT*64];
__device__ float  g_z3[(size_t)NSAMP_TOT*128];
__device__ double g_sum[3*128];
__device__ double g_ssq[3*128];

// ---------------- pack xyz -> float4 with norm (+ zero stats) -------------
__global__ void pack_kernel(const float* __restrict__ xyz) {
    int t = blockIdx.x*blockDim.x + threadIdx.x;
    if (blockIdx.x == 0) {
        for (int z = threadIdx.x; z < 384; z += 256) {
            g_sum[z] = 0.0; g_ssq[z] = 0.0;
        }
    }
    if (t >= NB*NPTS) return;
    int b = t >> 15, n = t & (NPTS-1);
    const float* p = xyz + (size_t)b*3*NPTS;
    float x = p[n], y = p[NPTS+n], z = p[2*NPTS+n];
    float nr = __fmaf_rn(z, z, __fmaf_rn(y, y, __fmul_rn(x, x)));
    g_xyz4[t] = make_float4(x, y, z, nr);
}

// ---------------- transpose points [B,D,N] -> [B,N,D] ----------------
__global__ void transpose_kernel(const float* __restrict__ pts) {
    __shared__ float tile[32][33];
    int b = blockIdx.z;
    int n0 = blockIdx.x*32, c0 = blockIdx.y*32;
    const float* src = pts + (size_t)b*ND*NPTS;
    for (int i = threadIdx.y; i < 32; i += 8)
        tile[i][threadIdx.x] = src[(size_t)(c0+i)*NPTS + n0 + threadIdx.x];
    __syncthreads();
    float* dst = g_ptsT + (size_t)b*NPTS*ND;
    for (int i = threadIdx.y; i < 32; i += 8)
        dst[(size_t)(n0+i)*ND + c0 + threadIdx.x] = tile[threadIdx.x][i];
}

// ---------------- FPS: 8-CTA cluster, coords-in-message -------------------
__device__ __forceinline__ unsigned smem_u32f(const void* p) {
    return (unsigned)__cvta_generic_to_shared(p);
}

__global__ void __cluster_dims__(8,1,1) __launch_bounds__(512,1)
fps_kernel(float* __restrict__ out) {
    cg::cluster_group cluster = cg::this_cluster();
    const int r = blockIdx.x;        // cluster rank 0..7
    const int b = blockIdx.y;        // batch
    const int t = threadIdx.x;       // 0..511
    const float4* pts = g_xyz4 + b*NPTS;
    const int base = r*4096;

    // register-resident slice: 8 points per thread
    float px[8], py[8], pz[8], d[8];
#pragma unroll
    for (int k = 0; k < 8; k++) {
        float4 p = __ldg(pts + base + k*512 + t);
        px[k] = p.x; py[k] = p.y; pz[k] = p.z; d[k] = 1e10f;
    }

    __shared__ unsigned long long sKey[16];
    __shared__ float sX[16], sY[16], sZ[16];
    __shared__ unsigned long long inbox[2][8][3];   // per rank: key,(x,y),(z)
    __shared__ unsigned long long mbar[2];

    const unsigned mbar_a0 = smem_u32f(&mbar[0]);
    const unsigned mbar_a1 = smem_u32f(&mbar[1]);
    const unsigned inb_a0  = smem_u32f(&inbox[0][r][0]);
    const unsigned inb_a1  = smem_u32f(&inbox[1][r][0]);

    if (t == 0) {
        asm volatile("mbarrier.init.shared.b64 [%0], %1;" :: "r"(mbar_a0), "r"(1u));
        asm volatile("mbarrier.init.shared.b64 [%0], %1;" :: "r"(mbar_a1), "r"(1u));
        // pre-arm BOTH barriers (it=0, it=1) before any remote can send
        asm volatile("mbarrier.arrive.expect_tx.shared.b64 _, [%0], %1;"
                     :: "r"(mbar_a0), "r"(192u) : "memory");
        asm volatile("mbarrier.arrive.expect_tx.shared.b64 _, [%0], %1;"
                     :: "r"(mbar_a1), "r"(192u) : "memory");
    }
    cluster.sync();   // arms + inits visible before any remote st.async

    float4 c0 = __ldg(pts);      // deterministic start at index 0
    float cx = c0.x, cy = c0.y, cz = c0.z;
    float* oxy = out + b*3*NS;

#pragma unroll 1
    for (int it = 0; it < NS; it++) {
        // output write on warp 15 — off the critical warp (warp 0, which
        // runs the tree scan + sends); warp 15 next only sleeps on mbarrier
        if (r == 0 && t == 480) {
            oxy[it]        = cx;
            oxy[NS + it]   = cy;
            oxy[2*NS + it] = cz;
            float nr = __fmaf_rn(cz, cz, __fmaf_rn(cy, cy, __fmul_rn(cx, cx)));
            g_newxyz[b*NS + it] = make_float4(cx, cy, cz, nr);
        }
        if (it == NS-1) break;

        const unsigned mb = (it & 1) ? mbar_a1 : mbar_a0;
        const unsigned ib = (it & 1) ? inb_a1  : inb_a0;
        const unsigned ph = (it >> 1) & 1;

        // local distance update + per-thread argmax (carry coords)
        float best = -1.0f, bx = 0.f, by = 0.f, bz = 0.f; int bi = 0;
#pragma unroll
        for (int k = 0; k < 8; k++) {
            float dx = px[k]-cx, dy = py[k]-cy, dz = pz[k]-cz;
            float dd = __fmaf_rn(dz, dz, __fmaf_rn(dy, dy, __fmul_rn(dx, dx)));
            float nd = fminf(d[k], dd);
            d[k] = nd;
            if (nd > best) { best = nd; bi = base + k*512 + t;
                             bx = px[k]; by = py[k]; bz = pz[k]; }
        }
        // warp argmax via HW redux: max dist bits, min idx among maxima
        unsigned db = __float_as_uint(best);
        unsigned mx = __reduce_max_sync(0xffffffffu, db);
        unsigned cand = (db == mx) ? (unsigned)bi : 0xffffffffu;
        unsigned bmin = __reduce_min_sync(0xffffffffu, cand);
        if (db == mx && (unsigned)bi == bmin) {   // exactly one lane per warp
            int w = t >> 5;
            sKey[w] = ((unsigned long long)mx << 32) | (unsigned)(~bmin);
            sX[w] = bx; sY[w] = by; sZ[w] = bz;
        }
        __syncthreads();   // SYNC1: sKey/sX/sY/sZ published to warp 0

        if (t < 32) {
            // depth-4 max tree over 16 warp candidates (index carried)
            unsigned long long ka[16];
#pragma unroll
            for (int w2 = 0; w2 < 16; w2++) ka[w2] = sKey[w2];
            unsigned long long k8[8]; int i8[8];
#pragma unroll
            for (int w2 = 0; w2 < 8; w2++) {
                bool g = ka[2*w2+1] > ka[2*w2];
                k8[w2] = g ? ka[2*w2+1] : ka[2*w2];
                i8[w2] = g ? 2*w2+1 : 2*w2;
            }
            unsigned long long k4[4]; int i4[4];
#pragma unroll
            for (int w2 = 0; w2 < 4; w2++) {
                bool g = k8[2*w2+1] > k8[2*w2];
                k4[w2] = g ? k8[2*w2+1] : k8[2*w2];
                i4[w2] = g ? i8[2*w2+1] : i8[2*w2];
            }
            bool g0 = k4[1] > k4[0];
            unsigned long long k20 = g0 ? k4[1] : k4[0];
            int i20 = g0 ? i4[1] : i4[0];
            bool g1 = k4[3] > k4[2];
            unsigned long long k21 = g1 ? k4[3] : k4[2];
            int i21 = g1 ? i4[3] : i4[2];
            bool gf = k21 > k20;
            unsigned long long bk = gf ? k21 : k20;
            int bw = gf ? i21 : i20;

            float wx = sX[bw], wy = sY[bw], wz = sZ[bw];
            unsigned long long m1 =
                ((unsigned long long)__float_as_uint(wy) << 32) | __float_as_uint(wx);
            unsigned long long m2 = (unsigned long long)__float_as_uint(wz);
            if (t < 8) {
                // lane t sends our 3-word message to rank t
                unsigned rem_a, rem_m;
                asm("mapa.shared::cluster.u32 %0, %1, %2;" : "=r"(rem_a) : "r"(ib), "r"(t));
                asm("mapa.shared::cluster.u32 %0, %1, %2;" : "=r"(rem_m) : "r"(mb), "r"(t));
                asm volatile(
                    "st.async.shared::cluster.mbarrier::complete_tx::bytes.b64 [%0], %1, [%2];"
                    :: "r"(rem_a), "l"(bk), "r"(rem_m) : "memory");
                asm volatile(
                    "st.async.shared::cluster.mbarrier::complete_tx::bytes.b64 [%0], %1, [%2];"
                    :: "r"(rem_a + 8u), "l"(m1), "r"(rem_m) : "memory");
                asm volatile(
                    "st.async.shared::cluster.mbarrier::complete_tx::bytes.b64 [%0], %1, [%2];"
                    :: "r"(rem_a + 16u), "l"(m2), "r"(rem_m) : "memory");
            }
        }

        // wait for all 8 messages (192 bytes)
        {
            unsigned done;
            asm volatile(
                "{\n\t.reg .pred p;\n\t"
                "mbarrier.try_wait.parity.acquire.cta.shared::cta.b64 p, [%1], %2;\n\t"
                "selp.b32 %0, 1, 0, p;\n\t}"
                : "=r"(done) : "r"(mb), "r"(ph) : "memory");
            if (!done) {
                asm volatile(
                    "{\n\t.reg .pred P1;\n\t"
                    "WL_%=:\n\t"
                    "mbarrier.try_wait.parity.acquire.cta.shared::cta.b64 P1, [%0], %1, 0x989680;\n\t"
                    "@P1 bra.uni WD_%=;\n\t"
                    "bra.uni WL_%=;\n\t"
                    "WD_%=:\n\t}"
                    :: "r"(mb), "r"(ph) : "memory");
            }
        }

        // re-arm THIS barrier for it+2 NOW — before our it+1 sends, which
        // gate every remote's it+2 sends: no complete_tx hits an unarmed bar
        if (t == 0)
            asm volatile("mbarrier.arrive.expect_tx.shared.b64 _, [%0], %1;"
                         :: "r"(mb), "r"(192u) : "memory");

        // reduce 8 candidates; winner's coords come from its message.
        // No trailing __syncthreads needed: overwrite of inbox[it&1] (at
        // it+2) requires our it+1 sends, which occur after SYNC1(it+1),
        // which every thread reaches only after finishing this read. sKey
        // writes at it+1 are gated by each warp's mbarrier wait(it).
        const unsigned long long (*in)[3] = inbox[(it & 1)];
        unsigned long long bk2 = in[0][0]; int bp = 0;
#pragma unroll
        for (int p = 1; p < 8; p++) {
            unsigned long long v = in[p][0];
            if (v > bk2) { bk2 = v; bp = p; }
        }
        unsigned long long cxy = in[bp][1];
        unsigned long long czw = in[bp][2];
        cx = __uint_as_float((unsigned)(cxy & 0xffffffffu));
        cy = __uint_as_float((unsigned)(cxy >> 32));
        cz = __uint_as_float((unsigned)(czw & 0xffffffffu));
    }
    cluster.sync();
}

// ---------------- ball query: warp per centroid, MLP=4 pipeline -----------
__global__ void ball_kernel() {
    int gid  = blockIdx.x*4 + (threadIdx.x >> 5);   // b*NS + s
    int lane = threadIdx.x & 31;
    int b = gid >> 10;
    const float4* pts = g_xyz4 + b*NPTS;
    float4 c4 = g_newxyz[gid];
    int* op = g_ballidx + gid*NK;
    int have = 0;
#pragma unroll 1
    for (int ch = 0; ch < NPTS/128 && have < NK; ch++) {
        int j0 = ch*128 + lane;
        float4 p0 = __ldg(pts + j0);
        float4 p1 = __ldg(pts + j0 + 32);
        float4 p2 = __ldg(pts + j0 + 64);
        float4 p3 = __ldg(pts + j0 + 96);
#pragma unroll
        for (int q = 0; q < 4; q++) {
            float4 p = (q == 0) ? p0 : (q == 1) ? p1 : (q == 2) ? p2 : p3;
            int j = j0 + q*32;
            float dot = __fmaf_rn(c4.z, p.z, __fmaf_rn(c4.y, p.y, __fmul_rn(c4.x, p.x)));
            float dd  = __fadd_rn(__fadd_rn(__fmul_rn(-2.0f, dot), c4.w), p.w);
            bool in = !(dd > R2);
            unsigned m = __ballot_sync(0xffffffffu, in);
            int pos = have + __popc(m & ((1u << lane) - 1u));
            if (in && pos < NK) op[pos] = j;
            have += __popc(m);
        }
    }
    if (have < NK && lane < NK - have) op[have + lane] = NPTS - 1;
}

// ---- fused per-CTA channel-stats epilogue (64 channels, layer offset) ----
__device__ __forceinline__ void stats_epilogue(float* sh, const float* acc,
                                               int layer_off) {
    __syncthreads();   // everyone done with previous contents of sh
    float* sS = sh;    // [64][257]
#pragma unroll
    for (int c = 0; c < 64; c++)
        sS[c*257 + threadIdx.x] = acc[c];
    __syncthreads();
    if (threadIdx.x < 64) {
        const float* row = sS + threadIdx.x*257;
        float s0=0.f,s1=0.f,s2=0.f,s3=0.f, q0=0.f,q1=0.f,q2=0.f,q3=0.f;
#pragma unroll 4
        for (int i = 0; i < 256; i += 4) {
            float v0 = row[i], v1 = row[i+1], v2 = row[i+2], v3 = row[i+3];
            s0 += v0; s1 += v1; s2 += v2; s3 += v3;
            q0 = __fmaf_rn(v0, v0, q0); q1 = __fmaf_rn(v1, v1, q1);
            q2 = __fmaf_rn(v2, v2, q2); q3 = __fmaf_rn(v3, v3, q3);
        }
        double s = (double)(s0+s1) + (double)(s2+s3);
        double q = (double)(q0+q1) + (double)(q2+q3);
        atomicAdd(&g_sum[layer_off + threadIdx.x], s);
        atomicAdd(&g_ssq[layer_off + threadIdx.x], q);
    }
}

// ---------------- conv1: gather feat (3+64) -> 64 ch (+stats) -------------
__global__ __launch_bounds__(256) void conv1_kernel(const float* __restrict__ w,
                                                    const float* __restrict__ bias) {
    extern __shared__ float sh[];
    float* sW = sh;                 // [67][64]
    float* sB = sh + 67*64;         // [64]
    float* sF = sh + 67*64 + 64;    // [256][67]
    for (int idx = threadIdx.x; idx < 67*64; idx += 256) {
        int c = idx >> 6, o = idx & 63;
        sW[idx] = w[o*67 + c];
    }
    if (threadIdx.x < 64) sB[threadIdx.x] = bias[threadIdx.x];
    __syncthreads();

    int i = blockIdx.x*256 + threadIdx.x;
    int b = i >> 15, s = (i >> 5) & 1023;
    int j = g_ballidx[i];
    float4 p  = __ldg(&g_xyz4[b*NPTS + j]);
    float4 c4 = g_newxyz[b*NS + s];
    float* f = sF + threadIdx.x*67;
    f[0] = p.x - c4.x; f[1] = p.y - c4.y; f[2] = p.z - c4.z;
    const float4* pr = (const float4*)(g_ptsT + ((size_t)b*NPTS + j)*ND);
#pragma unroll
    for (int q = 0; q < 16; q++) {
        float4 v = __ldg(pr + q);
        f[3+q*4] = v.x; f[4+q*4] = v.y; f[5+q*4] = v.z; f[6+q*4] = v.w;
    }

    float acc[64];
#pragma unroll
    for (int q = 0; q < 16; q++) {
        float4 v = *(const float4*)(sB + q*4);
        acc[q*4] = v.x; acc[q*4+1] = v.y; acc[q*4+2] = v.z; acc[q*4+3] = v.w;
    }
#pragma unroll 2
    for (int c = 0; c < 67; c++) {
        float fc = f[c];
        const float4* wr = (const float4*)(sW + c*64);
#pragma unroll
        for (int q = 0; q < 16; q++) {
            float4 wv = wr[q];
            acc[q*4+0] = __fmaf_rn(wv.x, fc, acc[q*4+0]);
            acc[q*4+1] = __fmaf_rn(wv.y, fc, acc[q*4+1]);
            acc[q*4+2] = __fmaf_rn(wv.z, fc, acc[q*4+2]);
            acc[q*4+3] = __fmaf_rn(wv.w, fc, acc[q*4+3]);
        }
    }
    float4* zo = (float4*)(g_z1 + (size_t)i*64);
#pragma unroll
    for (int q = 0; q < 16; q++)
        zo[q] = make_float4(acc[q*4], acc[q*4+1], acc[q*4+2], acc[q*4+3]);

    stats_epilogue(sh, acc, 0);
}

// ---------------- conv2: BN(z1)+ReLU -> 64 ch (+stats, fused finalize) ----
__global__ __launch_bounds__(256) void conv2_kernel(const float* __restrict__ w,
                                                    const float* __restrict__ bias,
                                                    const float* __restrict__ gam,
                                                    const float* __restrict__ bet) {
    extern __shared__ float sh[];
    float* sW  = sh;                // [64][64]
    float* sB  = sh + 4096;
    float* sA  = sB + 64;
    float* sS2 = sA + 64;
    float* sF  = sS2 + 64;          // [256][65]
    for (int idx = threadIdx.x; idx < 64*64; idx += 256) {
        int c = idx >> 6, o = idx & 63;
        sW[idx] = w[o*64 + c];
    }
    if (threadIdx.x < 64) {
        int c = threadIdx.x;
        sB[c] = bias[c];
        double mu  = g_sum[c] * (1.0/131072.0);
        double var = g_ssq[c] * (1.0/131072.0) - mu*mu;
        float aa = gam[c] * rsqrtf((float)var + 1e-5f);
        sA[c]  = aa;
        sS2[c] = bet[c] - (float)mu * aa;
    }
    __syncthreads();

    int i = blockIdx.x*256 + threadIdx.x;
    const float4* zr = (const float4*)(g_z1 + (size_t)i*64);
    float* f = sF + threadIdx.x*65;
#pragma unroll
    for (int q = 0; q < 16; q++) {
        float4 v = __ldg(zr + q);
        f[q*4+0] = fmaxf(__fmaf_rn(sA[q*4+0], v.x, sS2[q*4+0]), 0.f);
        f[q*4+1] = fmaxf(__fmaf_rn(sA[q*4+1], v.y, sS2[q*4+1]), 0.f);
        f[q*4+2] = fmaxf(__fmaf_rn(sA[q*4+2], v.z, sS2[q*4+2]), 0.f);
        f[q*4+3] = fmaxf(__fmaf_rn(sA[q*4+3], v.w, sS2[q*4+3]), 0.f);
    }

    float acc[64];
#pragma unroll
    for (int q = 0; q < 16; q++) {
        float4 v = *(const float4*)(sB + q*4);
        acc[q*4] = v.x; acc[q*4+1] = v.y; acc[q*4+2] = v.z; acc[q*4+3] = v.w;
    }
#pragma unroll 2
    for (int c = 0; c < 64; c++) {
        float fc = f[c];
        const float4* wr = (const float4*)(sW + c*64);
#pragma unroll
        for (int q = 0; q < 16; q++) {
            float4 wv = wr[q];
            acc[q*4+0] = __fmaf_rn(wv.x, fc, acc[q*4+0]);
            acc[q*4+1] = __fmaf_rn(wv.y, fc, acc[q*4+1]);
            acc[q*4+2] = __fmaf_rn(wv.z, fc, acc[q*4+2]);
            acc[q*4+3] = __fmaf_rn(wv.w, fc, acc[q*4+3]);
        }
    }
    float4* zo = (float4*)(g_z2 + (size_t)i*64);
#pragma unroll
    for (int q = 0; q < 16; q++)
        zo[q] = make_float4(acc[q*4], acc[q*4+1], acc[q*4+2], acc[q*4+3]);

    stats_epilogue(sh, acc, 128);
}

// ------- conv3: BN(z2)+ReLU -> 128 ch (2 halves, +stats, fused finalize) --
__global__ __launch_bounds__(256) void conv3_kernel(const float* __restrict__ w,
                                                    const float* __restrict__ bias,
                                                    const float* __restrict__ gam,
                                                    const float* __restrict__ bet) {
    extern __shared__ float sh[];
    float* sW  = sh;                // [64][64] (this half)
    float* sB  = sh + 4096;
    float* sA  = sB + 64;
    float* sS2 = sA + 64;
    float* sF  = sS2 + 64;          // [256][65]
    int half = blockIdx.y;
    for (int idx = threadIdx.x; idx < 64*64; idx += 256) {
        int c = idx >> 6, o = idx & 63;
        sW[idx] = w[((half << 6) + o)*64 + c];
    }
    if (threadIdx.x < 64) {
        int c = threadIdx.x;
        sB[c] = bias[(half << 6) + c];
        double mu  = g_sum[128 + c] * (1.0/131072.0);
        double var = g_ssq[128 + c] * (1.0/131072.0) - mu*mu;
        float aa = gam[c] * rsqrtf((float)var + 1e-5f);
        sA[c]  = aa;
        sS2[c] = bet[c] - (float)mu * aa;
    }
    __syncthreads();

    int i = blockIdx.x*256 + threadIdx.x;
    const float4* zr = (const float4*)(g_z2 + (size_t)i*64);
    float* f = sF + threadIdx.x*65;
#pragma unroll
    for (int q = 0; q < 16; q++) {
        float4 v = __ldg(zr + q);
        f[q*4+0] = fmaxf(__fmaf_rn(sA[q*4+0], v.x, sS2[q*4+0]), 0.f);
        f[q*4+1] = fmaxf(__fmaf_rn(sA[q*4+1], v.y, sS2[q*4+1]), 0.f);
        f[q*4+2] = fmaxf(__fmaf_rn(sA[q*4+2], v.z, sS2[q*4+2]), 0.f);
        f[q*4+3] = fmaxf(__fmaf_rn(sA[q*4+3], v.w, sS2[q*4+3]), 0.f);
    }

    float acc[64];
#pragma unroll
    for (int q = 0; q < 16; q++) {
        float4 v = *(const float4*)(sB + q*4);
        acc[q*4] = v.x; acc[q*4+1] = v.y; acc[q*4+2] = v.z; acc[q*4+3] = v.w;
    }
#pragma unroll 2
    for (int c = 0; c < 64; c++) {
        float fc = f[c];
        const float4* wr = (const float4*)(sW + c*64);
#pragma unroll
        for (int q = 0; q < 16; q++) {
            float4 wv = wr[q];
            acc[q*4+0] = __fmaf_rn(wv.x, fc, acc[q*4+0]);
            acc[q*4+1] = __fmaf_rn(wv.y, fc, acc[q*4+1]);
            acc[q*4+2] = __fmaf_rn(wv.z, fc, acc[q*4+2]);
            acc[q*4+3] = __fmaf_rn(wv.w, fc, acc[q*4+3]);
        }
    }
    float4* zo = (float4*)(g_z3 + (size_t)i*128 + (half << 6));
#pragma unroll
    for (int q = 0; q < 16; q++)
        zo[q] = make_float4(acc[q*4], acc[q*4+1], acc[q*4+2], acc[q*4+3]);

    stats_epilogue(sh, acc, 256 + (half << 6));
}

// ------- BN+ReLU+maxpool over K -> output (fused finalize, fp32 path) -----
__global__ void maxpool_kernel(float* __restrict__ out,
                               const float* __restrict__ gam,
                               const float* __restrict__ bet) {
    int bs = blockIdx.x;              // b*NS + s
    int o  = threadIdx.x;             // 0..127
    const float* z = g_z3 + (size_t)bs*NK*128;
    float mu  = __double2float_rn(g_sum[256 + o]) * (1.0f/131072.0f);
    float ex2 = __double2float_rn(g_ssq[256 + o]) * (1.0f/131072.0f);
    float var = ex2 - mu*mu;
    float a   = gam[o] * rsqrtf(var + 1e-5f);
    float sh  = bet[o] - mu * a;
    float m = -1e30f;
#pragma unroll
    for (int k = 0; k < NK; k++) {
        float v = fmaxf(__fmaf_rn(a, z[k*128 + o], sh), 0.f);
        m = fmaxf(m, v);
    }
    int b = bs >> 10, s = bs & 1023;
    out[NB*3*NS + ((size_t)(b*128 + o))*NS + s] = m;
}

// ---------------- launch ----------------
extern "C" void kernel_launch(void* const* d_in, const int* in_sizes, int n_in,
                              void* d_out, int out_size) {
    const float* xyz = (const float*)d_in[0];
    const float* pts = (const float*)d_in[1];
    const float* w0  = (const float*)d_in[2];
    const float* b0  = (const float*)d_in[3];
    const float* g0  = (const float*)d_in[4];
    const float* t0  = (const float*)d_in[5];
    const float* w1  = (const float*)d_in[6];
    const float* b1  = (const float*)d_in[7];
    const float* g1  = (const float*)d_in[8];
    const float* t1  = (const float*)d_in[9];
    const float* w2  = (const float*)d_in[10];
    const float* b2  = (const float*)d_in[11];
    const float* g2  = (const float*)d_in[12];
    const float* t2  = (const float*)d_in[13];
    float* out = (float*)d_out;

    const int SH1 = (67*64 + 64 + 256*67) * 4;           // 86016 (>= 64*257*4)
    const int SH2 = (64*64 + 64 + 64 + 64 + 256*65) * 4; // 83712 (>= 64*257*4)
    cudaFuncSetAttribute(conv1_kernel, cudaFuncAttributeMaxDynamicSharedMemorySize, SH1);
    cudaFuncSetAttribute(conv2_kernel, cudaFuncAttributeMaxDynamicSharedMemorySize, SH2);
    cudaFuncSetAttribute(conv3_kernel, cudaFuncAttributeMaxDynamicSharedMemorySize, SH2);

    pack_kernel<<<(NB*NPTS + 255)/256, 256>>>(xyz);
    transpose_kernel<<<dim3(NPTS/32, ND/32, NB), dim3(32, 8)>>>(pts);
    fps_kernel<<<dim3(8, NB), 512>>>(out);
    ball_kernel<<<NB*NS/4, 128>>>();
    conv1_kernel<<<NSAMP_TOT/256, 256, SH1>>>(w0, b0);
    conv2_kernel<<<NSAMP_TOT/256, 256, SH2>>>(w1, b1, g0, t0);
    conv3_kernel<<<dim3(NSAMP_TOT/256, 2), 256, SH2>>>(w2, b2, g1, t1);
    maxpool_kernel<<<NB*NS, 128>>>(out, g2, t2);
}

// round 13
// speedup vs baseline: 1.0922x; 1.0922x over previous
#include <cuda_runtime.h>
#include <cooperative_groups.h>
namespace cg = cooperative_groups;

#define NB 4
#define NPTS 32768
#define NS 1024
#define NK 32
#define ND 64
#define NSAMP_TOT (NB*NS*NK)   // 131072
#define R2 0.04f

// ---------------- device scratch (static, allowed) ----------------
__device__ float4 g_xyz4[NB*NPTS];                    // x,y,z, |p|^2
__device__ float  g_ptsT[(size_t)NB*NPTS*ND];         // [b][n][c]
__device__ float4 g_newxyz[NB*NS];                    // centroid + |c|^2
__device__ int    g_ballidx[NB*NS*NK];
__device__ float  g_z1[(size_t)NSAMP_TOT*64];
__device__ float  g_z2[(size_t)NSAMP_TOT*64];
__device__ float  g_z3[(size_t)NSAMP_TOT*128];
__device__ double g_sum[3*128];
__device__ double g_ssq[3*128];

// ---------------- pack xyz -> float4 with norm (+ zero stats) -------------
__global__ void pack_kernel(const float* __restrict__ xyz) {
    int t = blockIdx.x*blockDim.x + threadIdx.x;
    if (blockIdx.x == 0) {
        for (int z = threadIdx.x; z < 384; z += 256) {
            g_sum[z] = 0.0; g_ssq[z] = 0.0;
        }
    }
    if (t >= NB*NPTS) return;
    int b = t >> 15, n = t & (NPTS-1);
    const float* p = xyz + (size_t)b*3*NPTS;
    float x = p[n], y = p[NPTS+n], z = p[2*NPTS+n];
    float nr = __fmaf_rn(z, z, __fmaf_rn(y, y, __fmul_rn(x, x)));
    g_xyz4[t] = make_float4(x, y, z, nr);
}

// ---------------- transpose points [B,D,N] -> [B,N,D] ----------------
__global__ void transpose_kernel(const float* __restrict__ pts) {
    __shared__ float tile[32][33];
    int b = blockIdx.z;
    int n0 = blockIdx.x*32, c0 = blockIdx.y*32;
    const float* src = pts + (size_t)b*ND*NPTS;
    for (int i = threadIdx.y; i < 32; i += 8)
        tile[i][threadIdx.x] = src[(size_t)(c0+i)*NPTS + n0 + threadIdx.x];
    __syncthreads();
    float* dst = g_ptsT + (size_t)b*NPTS*ND;
    for (int i = threadIdx.y; i < 32; i += 8)
        dst[(size_t)(n0+i)*ND + c0 + threadIdx.x] = tile[threadIdx.x][i];
}

// ---------------- FPS: 8-CTA cluster, coords-in-message -------------------
__device__ __forceinline__ unsigned smem_u32f(const void* p) {
    return (unsigned)__cvta_generic_to_shared(p);
}

__global__ void __cluster_dims__(8,1,1) __launch_bounds__(512,1)
fps_kernel(float* __restrict__ out) {
    cg::cluster_group cluster = cg::this_cluster();
    const int r = blockIdx.x;        // cluster rank 0..7
    const int b = blockIdx.y;        // batch
    const int t = threadIdx.x;       // 0..511
    const float4* pts = g_xyz4 + b*NPTS;
    const int base = r*4096;

    // register-resident slice: 8 points per thread
    float px[8], py[8], pz[8], d[8];
#pragma unroll
    for (int k = 0; k < 8; k++) {
        float4 p = __ldg(pts + base + k*512 + t);
        px[k] = p.x; py[k] = p.y; pz[k] = p.z; d[k] = 1e10f;
    }

    __shared__ unsigned long long sKey[16];
    __shared__ float sX[16], sY[16], sZ[16];
    __shared__ unsigned long long inbox[2][8][3];   // per rank: key,(x,y),(z)
    __shared__ unsigned long long mbar[2];
    __shared__ float4 sOut[NS];     // staged centroids (rank 0 only)

    const unsigned mbar_a0 = smem_u32f(&mbar[0]);
    const unsigned mbar_a1 = smem_u32f(&mbar[1]);
    const unsigned inb_a0  = smem_u32f(&inbox[0][r][0]);
    const unsigned inb_a1  = smem_u32f(&inbox[1][r][0]);

    if (t == 0) {
        asm volatile("mbarrier.init.shared.b64 [%0], %1;" :: "r"(mbar_a0), "r"(1u));
        asm volatile("mbarrier.init.shared.b64 [%0], %1;" :: "r"(mbar_a1), "r"(1u));
        // pre-arm BOTH barriers (it=0, it=1) before any remote can send
        asm volatile("mbarrier.arrive.expect_tx.shared.b64 _, [%0], %1;"
                     :: "r"(mbar_a0), "r"(192u) : "memory");
        asm volatile("mbarrier.arrive.expect_tx.shared.b64 _, [%0], %1;"
                     :: "r"(mbar_a1), "r"(192u) : "memory");
    }
    cluster.sync();   // arms + inits visible before any remote st.async

    float4 c0 = __ldg(pts);      // deterministic start at index 0
    float cx = c0.x, cy = c0.y, cz = c0.z;

#pragma unroll 1
    for (int it = 0; it < NS; it++) {
        // stage centroid to shared (single STS, no STG / nr chain in loop)
        if (r == 0 && t == 0)
            sOut[it] = make_float4(cx, cy, cz, 0.f);
        if (it == NS-1) break;

        const unsigned mb = (it & 1) ? mbar_a1 : mbar_a0;
        const unsigned ib = (it & 1) ? inb_a1  : inb_a0;
        const unsigned ph = (it >> 1) & 1;

        // local distance update + per-thread argmax (carry coords)
        float best = -1.0f, bx = 0.f, by = 0.f, bz = 0.f; int bi = 0;
#pragma unroll
        for (int k = 0; k < 8; k++) {
            float dx = px[k]-cx, dy = py[k]-cy, dz = pz[k]-cz;
            float dd = __fmaf_rn(dz, dz, __fmaf_rn(dy, dy, __fmul_rn(dx, dx)));
            float nd = fminf(d[k], dd);
            d[k] = nd;
            if (nd > best) { best = nd; bi = base + k*512 + t;
                             bx = px[k]; by = py[k]; bz = pz[k]; }
        }
        // warp argmax via HW redux: max dist bits, min idx among maxima
        unsigned db = __float_as_uint(best);
        unsigned mx = __reduce_max_sync(0xffffffffu, db);
        unsigned cand = (db == mx) ? (unsigned)bi : 0xffffffffu;
        unsigned bmin = __reduce_min_sync(0xffffffffu, cand);
        if (db == mx && (unsigned)bi == bmin) {   // exactly one lane per warp
            int w = t >> 5;
            sKey[w] = ((unsigned long long)mx << 32) | (unsigned)(~bmin);
            sX[w] = bx; sY[w] = by; sZ[w] = bz;
        }
        __syncthreads();   // SYNC1: sKey/sX/sY/sZ published to warp 0

        if (t < 32) {
            // depth-4 max tree over 16 warp candidates (index carried)
            unsigned long long ka[16];
#pragma unroll
            for (int w2 = 0; w2 < 16; w2++) ka[w2] = sKey[w2];
            unsigned long long k8[8]; int i8[8];
#pragma unroll
            for (int w2 = 0; w2 < 8; w2++) {
                bool g = ka[2*w2+1] > ka[2*w2];
                k8[w2] = g ? ka[2*w2+1] : ka[2*w2];
                i8[w2] = g ? 2*w2+1 : 2*w2;
            }
            unsigned long long k4[4]; int i4[4];
#pragma unroll
            for (int w2 = 0; w2 < 4; w2++) {
                bool g = k8[2*w2+1] > k8[2*w2];
                k4[w2] = g ? k8[2*w2+1] : k8[2*w2];
                i4[w2] = g ? i8[2*w2+1] : i8[2*w2];
            }
            bool g0 = k4[1] > k4[0];
            unsigned long long k20 = g0 ? k4[1] : k4[0];
            int i20 = g0 ? i4[1] : i4[0];
            bool g1 = k4[3] > k4[2];
            unsigned long long k21 = g1 ? k4[3] : k4[2];
            int i21 = g1 ? i4[3] : i4[2];
            bool gf = k21 > k20;
            unsigned long long bk = gf ? k21 : k20;
            int bw = gf ? i21 : i20;

            float wx = sX[bw], wy = sY[bw], wz = sZ[bw];
            unsigned long long m1 =
                ((unsigned long long)__float_as_uint(wy) << 32) | __float_as_uint(wx);
            unsigned long long m2 = (unsigned long long)__float_as_uint(wz);
            if (t < 8) {
                // lane t sends our 3-word message to rank t
                unsigned rem_a, rem_m;
                asm("mapa.shared::cluster.u32 %0, %1, %2;" : "=r"(rem_a) : "r"(ib), "r"(t));
                asm("mapa.shared::cluster.u32 %0, %1, %2;" : "=r"(rem_m) : "r"(mb), "r"(t));
                asm volatile(
                    "st.async.shared::cluster.mbarrier::complete_tx::bytes.b64 [%0], %1, [%2];"
                    :: "r"(rem_a), "l"(bk), "r"(rem_m) : "memory");
                asm volatile(
                    "st.async.shared::cluster.mbarrier::complete_tx::bytes.b64 [%0], %1, [%2];"
                    :: "r"(rem_a + 8u), "l"(m1), "r"(rem_m) : "memory");
                asm volatile(
                    "st.async.shared::cluster.mbarrier::complete_tx::bytes.b64 [%0], %1, [%2];"
                    :: "r"(rem_a + 16u), "l"(m2), "r"(rem_m) : "memory");
            }
        }

        // wait for all 8 messages (192 bytes)
        {
            unsigned done;
            asm volatile(
                "{\n\t.reg .pred p;\n\t"
                "mbarrier.try_wait.parity.acquire.cta.shared::cta.b64 p, [%1], %2;\n\t"
                "selp.b32 %0, 1, 0, p;\n\t}"
                : "=r"(done) : "r"(mb), "r"(ph) : "memory");
            if (!done) {
                asm volatile(
                    "{\n\t.reg .pred P1;\n\t"
                    "WL_%=:\n\t"
                    "mbarrier.try_wait.parity.acquire.cta.shared::cta.b64 P1, [%0], %1, 0x989680;\n\t"
                    "@P1 bra.uni WD_%=;\n\t"
                    "bra.uni WL_%=;\n\t"
                    "WD_%=:\n\t}"
                    :: "r"(mb), "r"(ph) : "memory");
            }
        }

        // re-arm THIS barrier for it+2 NOW — before our it+1 sends, which
        // gate every remote's it+2 sends: no complete_tx hits an unarmed bar
        if (t == 0)
            asm volatile("mbarrier.arrive.expect_tx.shared.b64 _, [%0], %1;"
                         :: "r"(mb), "r"(192u) : "memory");

        // reduce 8 candidates; winner's coords come from its message.
        // No trailing __syncthreads needed: overwrite of inbox[it&1] (at
        // it+2) requires our it+1 sends, which occur after SYNC1(it+1),
        // which every thread reaches only after finishing this read. sKey
        // writes at it+1 are gated by each warp's mbarrier wait(it).
        const unsigned long long (*in)[3] = inbox[(it & 1)];
        unsigned long long bk2 = in[0][0]; int bp = 0;
#pragma unroll
        for (int p = 1; p < 8; p++) {
            unsigned long long v = in[p][0];
            if (v > bk2) { bk2 = v; bp = p; }
        }
        unsigned long long cxy = in[bp][1];
        unsigned long long czw = in[bp][2];
        cx = __uint_as_float((unsigned)(cxy & 0xffffffffu));
        cy = __uint_as_float((unsigned)(cxy >> 32));
        cz = __uint_as_float((unsigned)(czw & 0xffffffffu));
    }

    // bulk write of staged centroids (rank 0 CTAs only)
    __syncthreads();
    if (r == 0) {
        float* oxy = out + b*3*NS;
#pragma unroll 1
        for (int i2 = t; i2 < NS; i2 += 512) {
            float4 c = sOut[i2];
            oxy[i2]        = c.x;
            oxy[NS + i2]   = c.y;
            oxy[2*NS + i2] = c.z;
            float nr = __fmaf_rn(c.z, c.z, __fmaf_rn(c.y, c.y, __fmul_rn(c.x, c.x)));
            g_newxyz[b*NS + i2] = make_float4(c.x, c.y, c.z, nr);
        }
    }
    cluster.sync();
}

// ---------------- ball query: warp per centroid, MLP=4 pipeline -----------
__global__ void ball_kernel() {
    int gid  = blockIdx.x*4 + (threadIdx.x >> 5);   // b*NS + s
    int lane = threadIdx.x & 31;
    int b = gid >> 10;
    const float4* pts = g_xyz4 + b*NPTS;
    float4 c4 = g_newxyz[gid];
    int* op = g_ballidx + gid*NK;
    int have = 0;
#pragma unroll 1
    for (int ch = 0; ch < NPTS/128 && have < NK; ch++) {
        int j0 = ch*128 + lane;
        float4 p0 = __ldg(pts + j0);
        float4 p1 = __ldg(pts + j0 + 32);
        float4 p2 = __ldg(pts + j0 + 64);
        float4 p3 = __ldg(pts + j0 + 96);
#pragma unroll
        for (int q = 0; q < 4; q++) {
            float4 p = (q == 0) ? p0 : (q == 1) ? p1 : (q == 2) ? p2 : p3;
            int j = j0 + q*32;
            float dot = __fmaf_rn(c4.z, p.z, __fmaf_rn(c4.y, p.y, __fmul_rn(c4.x, p.x)));
            float dd  = __fadd_rn(__fadd_rn(__fmul_rn(-2.0f, dot), c4.w), p.w);
            bool in = !(dd > R2);
            unsigned m = __ballot_sync(0xffffffffu, in);
            int pos = have + __popc(m & ((1u << lane) - 1u));
            if (in && pos < NK) op[pos] = j;
            have += __popc(m);
        }
    }
    if (have < NK && lane < NK - have) op[have + lane] = NPTS - 1;
}

// ---- fused per-CTA channel-stats epilogue (64 channels, layer offset) ----
__device__ __forceinline__ void stats_epilogue(float* sh, const float* acc,
                                               int layer_off) {
    __syncthreads();   // everyone done with previous contents of sh
    float* sS = sh;    // [64][257]
#pragma unroll
    for (int c = 0; c < 64; c++)
        sS[c*257 + threadIdx.x] = acc[c];
    __syncthreads();
    if (threadIdx.x < 64) {
        const float* row = sS + threadIdx.x*257;
        float s0=0.f,s1=0.f,s2=0.f,s3=0.f, q0=0.f,q1=0.f,q2=0.f,q3=0.f;
#pragma unroll 4
        for (int i = 0; i < 256; i += 4) {
            float v0 = row[i], v1 = row[i+1], v2 = row[i+2], v3 = row[i+3];
            s0 += v0; s1 += v1; s2 += v2; s3 += v3;
            q0 = __fmaf_rn(v0, v0, q0); q1 = __fmaf_rn(v1, v1, q1);
            q2 = __fmaf_rn(v2, v2, q2); q3 = __fmaf_rn(v3, v3, q3);
        }
        double s = (double)(s0+s1) + (double)(s2+s3);
        double q = (double)(q0+q1) + (double)(q2+q3);
        atomicAdd(&g_sum[layer_off + threadIdx.x], s);
        atomicAdd(&g_ssq[layer_off + threadIdx.x], q);
    }
}

// ---------------- conv1: gather feat (3+64) -> 64 ch (+stats) -------------
__global__ __launch_bounds__(256) void conv1_kernel(const float* __restrict__ w,
                                                    const float* __restrict__ bias) {
    extern __shared__ float sh[];
    float* sW = sh;                 // [67][64]
    float* sB = sh + 67*64;         // [64]
    float* sF = sh + 67*64 + 64;    // [256][67]
    for (int idx = threadIdx.x; idx < 67*64; idx += 256) {
        int c = idx >> 6, o = idx & 63;
        sW[idx] = w[o*67 + c];
    }
    if (threadIdx.x < 64) sB[threadIdx.x] = bias[threadIdx.x];
    __syncthreads();

    int i = blockIdx.x*256 + threadIdx.x;
    int b = i >> 15, s = (i >> 5) & 1023;
    int j = g_ballidx[i];
    float4 p  = __ldg(&g_xyz4[b*NPTS + j]);
    float4 c4 = g_newxyz[b*NS + s];
    float* f = sF + threadIdx.x*67;
    f[0] = p.x - c4.x; f[1] = p.y - c4.y; f[2] = p.z - c4.z;
    const float4* pr = (const float4*)(g_ptsT + ((size_t)b*NPTS + j)*ND);
#pragma unroll
    for (int q = 0; q < 16; q++) {
        float4 v = __ldg(pr + q);
        f[3+q*4] = v.x; f[4+q*4] = v.y; f[5+q*4] = v.z; f[6+q*4] = v.w;
    }

    float acc[64];
#pragma unroll
    for (int q = 0; q < 16; q++) {
        float4 v = *(const float4*)(sB + q*4);
        acc[q*4] = v.x; acc[q*4+1] = v.y; acc[q*4+2] = v.z; acc[q*4+3] = v.w;
    }
#pragma unroll 1
    for (int c = 0; c < 67; c++) {
        float fc = f[c];
        const float4* wr = (const float4*)(sW + c*64);
#pragma unroll
        for (int q = 0; q < 16; q++) {
            float4 wv = wr[q];
            acc[q*4+0] = __fmaf_rn(wv.x, fc, acc[q*4+0]);
            acc[q*4+1] = __fmaf_rn(wv.y, fc, acc[q*4+1]);
            acc[q*4+2] = __fmaf_rn(wv.z, fc, acc[q*4+2]);
            acc[q*4+3] = __fmaf_rn(wv.w, fc, acc[q*4+3]);
        }
    }
    float4* zo = (float4*)(g_z1 + (size_t)i*64);
#pragma unroll
    for (int q = 0; q < 16; q++)
        zo[q] = make_float4(acc[q*4], acc[q*4+1], acc[q*4+2], acc[q*4+3]);

    stats_epilogue(sh, acc, 0);
}

// ---------------- conv2: BN(z1)+ReLU -> 64 ch (+stats, fused finalize) ----
__global__ __launch_bounds__(256) void conv2_kernel(const float* __restrict__ w,
                                                    const float* __restrict__ bias,
                                                    const float* __restrict__ gam,
                                                    const float* __restrict__ bet) {
    extern __shared__ float sh[];
    float* sW  = sh;                // [64][64]
    float* sB  = sh + 4096;
    float* sA  = sB + 64;
    float* sS2 = sA + 64;
    float* sF  = sS2 + 64;          // [256][65]
    for (int idx = threadIdx.x; idx < 64*64; idx += 256) {
        int c = idx >> 6, o = idx & 63;
        sW[idx] = w[o*64 + c];
    }
    if (threadIdx.x < 64) {
        int c = threadIdx.x;
        sB[c] = bias[c];
        double mu  = g_sum[c] * (1.0/131072.0);
        double var = g_ssq[c] * (1.0/131072.0) - mu*mu;
        float aa = gam[c] * rsqrtf((float)var + 1e-5f);
        sA[c]  = aa;
        sS2[c] = bet[c] - (float)mu * aa;
    }
    __syncthreads();

    int i = blockIdx.x*256 + threadIdx.x;
    const float4* zr = (const float4*)(g_z1 + (size_t)i*64);
    float* f = sF + threadIdx.x*65;
#pragma unroll
    for (int q = 0; q < 16; q++) {
        float4 v = __ldg(zr + q);
        f[q*4+0] = fmaxf(__fmaf_rn(sA[q*4+0], v.x, sS2[q*4+0]), 0.f);
        f[q*4+1] = fmaxf(__fmaf_rn(sA[q*4+1], v.y, sS2[q*4+1]), 0.f);
        f[q*4+2] = fmaxf(__fmaf_rn(sA[q*4+2], v.z, sS2[q*4+2]), 0.f);
        f[q*4+3] = fmaxf(__fmaf_rn(sA[q*4+3], v.w, sS2[q*4+3]), 0.f);
    }

    float acc[64];
#pragma unroll
    for (int q = 0; q < 16; q++) {
        float4 v = *(const float4*)(sB + q*4);
        acc[q*4] = v.x; acc[q*4+1] = v.y; acc[q*4+2] = v.z; acc[q*4+3] = v.w;
    }
#pragma unroll 1
    for (int c = 0; c < 64; c++) {
        float fc = f[c];
        const float4* wr = (const float4*)(sW + c*64);
#pragma unroll
        for (int q = 0; q < 16; q++) {
            float4 wv = wr[q];
            acc[q*4+0] = __fmaf_rn(wv.x, fc, acc[q*4+0]);
            acc[q*4+1] = __fmaf_rn(wv.y, fc, acc[q*4+1]);
            acc[q*4+2] = __fmaf_rn(wv.z, fc, acc[q*4+2]);
            acc[q*4+3] = __fmaf_rn(wv.w, fc, acc[q*4+3]);
        }
    }
    float4* zo = (float4*)(g_z2 + (size_t)i*64);
#pragma unroll
    for (int q = 0; q < 16; q++)
        zo[q] = make_float4(acc[q*4], acc[q*4+1], acc[q*4+2], acc[q*4+3]);

    stats_epilogue(sh, acc, 128);
}

// ------- conv3: BN(z2)+ReLU -> 128 ch (2 halves, +stats, fused finalize) --
__global__ __launch_bounds__(256) void conv3_kernel(const float* __restrict__ w,
                                                    const float* __restrict__ bias,
                                                    const float* __restrict__ gam,
                                                    const float* __restrict__ bet) {
    extern __shared__ float sh[];
    float* sW  = sh;                // [64][64] (this half)
    float* sB  = sh + 4096;
    float* sA  = sB + 64;
    float* sS2 = sA + 64;
    float* sF  = sS2 + 64;          // [256][65]
    int half = blockIdx.y;
    for (int idx = threadIdx.x; idx < 64*64; idx += 256) {
        int c = idx >> 6, o = idx & 63;
        sW[idx] = w[((half << 6) + o)*64 + c];
    }
    if (threadIdx.x < 64) {
        int c = threadIdx.x;
        sB[c] = bias[(half << 6) + c];
        double mu  = g_sum[128 + c] * (1.0/131072.0);
        double var = g_ssq[128 + c] * (1.0/131072.0) - mu*mu;
        float aa = gam[c] * rsqrtf((float)var + 1e-5f);
        sA[c]  = aa;
        sS2[c] = bet[c] - (float)mu * aa;
    }
    __syncthreads();

    int i = blockIdx.x*256 + threadIdx.x;
    const float4* zr = (const float4*)(g_z2 + (size_t)i*64);
    float* f = sF + threadIdx.x*65;
#pragma unroll
    for (int q = 0; q < 16; q++) {
        float4 v = __ldg(zr + q);
        f[q*4+0] = fmaxf(__fmaf_rn(sA[q*4+0], v.x, sS2[q*4+0]), 0.f);
        f[q*4+1] = fmaxf(__fmaf_rn(sA[q*4+1], v.y, sS2[q*4+1]), 0.f);
        f[q*4+2] = fmaxf(__fmaf_rn(sA[q*4+2], v.z, sS2[q*4+2]), 0.f);
        f[q*4+3] = fmaxf(__fmaf_rn(sA[q*4+3], v.w, sS2[q*4+3]), 0.f);
    }

    float acc[64];
#pragma unroll
    for (int q = 0; q < 16; q++) {
        float4 v = *(const float4*)(sB + q*4);
        acc[q*4] = v.x; acc[q*4+1] = v.y; acc[q*4+2] = v.z; acc[q*4+3] = v.w;
    }
#pragma unroll 1
    for (int c = 0; c < 64; c++) {
        float fc = f[c];
        const float4* wr = (const float4*)(sW + c*64);
#pragma unroll
        for (int q = 0; q < 16; q++) {
            float4 wv = wr[q];
            acc[q*4+0] = __fmaf_rn(wv.x, fc, acc[q*4+0]);
            acc[q*4+1] = __fmaf_rn(wv.y, fc, acc[q*4+1]);
            acc[q*4+2] = __fmaf_rn(wv.z, fc, acc[q*4+2]);
            acc[q*4+3] = __fmaf_rn(wv.w, fc, acc[q*4+3]);
        }
    }
    float4* zo = (float4*)(g_z3 + (size_t)i*128 + (half << 6));
#pragma unroll
    for (int q = 0; q < 16; q++)
        zo[q] = make_float4(acc[q*4], acc[q*4+1], acc[q*4+2], acc[q*4+3]);

    stats_epilogue(sh, acc, 256 + (half << 6));
}

// ------- BN+ReLU+maxpool over K -> output (fused finalize, fp32 path) -----
__global__ void maxpool_kernel(float* __restrict__ out,
                               const float* __restrict__ gam,
                               const float* __restrict__ bet) {
    int bs = blockIdx.x;              // b*NS + s
    int o  = threadIdx.x;             // 0..127
    const float* z = g_z3 + (size_t)bs*NK*128;
    float mu  = __double2float_rn(g_sum[256 + o]) * (1.0f/131072.0f);
    float ex2 = __double2float_rn(g_ssq[256 + o]) * (1.0f/131072.0f);
    float var = ex2 - mu*mu;
    float a   = gam[o] * rsqrtf(var + 1e-5f);
    float sh  = bet[o] - mu * a;
    float m = -1e30f;
#pragma unroll
    for (int k = 0; k < NK; k++) {
        float v = fmaxf(__fmaf_rn(a, z[k*128 + o], sh), 0.f);
        m = fmaxf(m, v);
    }
    int b = bs >> 10, s = bs & 1023;
    out[NB*3*NS + ((size_t)(b*128 + o))*NS + s] = m;
}

// ---------------- launch ----------------
extern "C" void kernel_launch(void* const* d_in, const int* in_sizes, int n_in,
                              void* d_out, int out_size) {
    const float* xyz = (const float*)d_in[0];
    const float* pts = (const float*)d_in[1];
    const float* w0  = (const float*)d_in[2];
    const float* b0  = (const float*)d_in[3];
    const float* g0  = (const float*)d_in[4];
    const float* t0  = (const float*)d_in[5];
    const float* w1  = (const float*)d_in[6];
    const float* b1  = (const float*)d_in[7];
    const float* g1  = (const float*)d_in[8];
    const float* t1  = (const float*)d_in[9];
    const float* w2  = (const float*)d_in[10];
    const float* b2  = (const float*)d_in[11];
    const float* g2  = (const float*)d_in[12];
    const float* t2  = (const float*)d_in[13];
    float* out = (float*)d_out;

    const int SH1 = (67*64 + 64 + 256*67) * 4;           // 86016 (>= 64*257*4)
    const int SH2 = (64*64 + 64 + 64 + 64 + 256*65) * 4; // 83712 (>= 64*257*4)
    cudaFuncSetAttribute(conv1_kernel, cudaFuncAttributeMaxDynamicSharedMemorySize, SH1);
    cudaFuncSetAttribute(conv2_kernel, cudaFuncAttributeMaxDynamicSharedMemorySize, SH2);
    cudaFuncSetAttribute(conv3_kernel, cudaFuncAttributeMaxDynamicSharedMemorySize, SH2);

    pack_kernel<<<(NB*NPTS + 255)/256, 256>>>(xyz);
    transpose_kernel<<<dim3(NPTS/32, ND/32, NB), dim3(32, 8)>>>(pts);
    fps_kernel<<<dim3(8, NB), 512>>>(out);
    ball_kernel<<<NB*NS/4, 128>>>();
    conv1_kernel<<<NSAMP_TOT/256, 256, SH1>>>(w0, b0);
    conv2_kernel<<<NSAMP_TOT/256, 256, SH2>>>(w1, b1, g0, t0);
    conv3_kernel<<<dim3(NSAMP_TOT/256, 2), 256, SH2>>>(w2, b2, g1, t1);
    maxpool_kernel<<<NB*NS, 128>>>(out, g2, t2);
}